// round 14
// baseline (speedup 1.0000x reference)
#include <cuda_runtime.h>
#include <cstdint>

#define Nn     4096
#define IND    256
#define HH     4
#define DD     64
#define HD     256
#define JSPLIT 4
#define BM     128
#define BK     32
#define NCH    ((Nn / JSPLIT) / BK)     // 32 chunks
#define SWP    36                        // sW row stride (floats) -> conflict-free frags

// ---------------- scratch (device globals; no allocation allowed) ------------
__device__ __align__(16) float g_Wh [Nn * HD];            // fp32 Wh [node][h*64+d]
__device__ __align__(16) float g_Yp [HH * 512 * DD * 8];  // tf32 [h][g][d][jj'] frag order
__device__ __align__(16) float g_Ei1[Nn * HH];            // exp(e_i)
__device__ __align__(16) float g_Ei2[Nn * HH];            // exp(0.2 e_i)
__device__ __align__(16) float g_Ej1[Nn * HH];            // exp(e_j)
__device__ __align__(16) float g_Ej2[Nn * HH];            // exp(0.2 e_j)
__device__ __align__(16) float g_part[JSPLIT][Nn * HD];
__device__ __align__(16) float g_denp[JSPLIT][Nn * HH];
__device__ int g_nop;

__device__ __forceinline__ unsigned tf32r(float x) {
    unsigned u;
    asm("cvt.rna.tf32.f32 %0, %1;" : "=r"(u) : "f"(x));
    return u;
}
__device__ __forceinline__ void mma8(float* c, const unsigned* a, unsigned b0, unsigned b1) {
    asm volatile(
        "mma.sync.aligned.m16n8k8.row.col.f32.tf32.tf32.f32 "
        "{%0,%1,%2,%3}, {%4,%5,%6,%7}, {%8,%9}, {%0,%1,%2,%3};"
        : "+f"(c[0]), "+f"(c[1]), "+f"(c[2]), "+f"(c[3])
        : "r"(a[0]), "r"(a[1]), "r"(a[2]), "r"(a[3]), "r"(b0), "r"(b1));
}

// dummy launch: keeps ncu's fixed capture slot on k3
__global__ void k0_nop() { g_nop = 0; }

// forward perm: j-within-8 -> storage position in g_Yp frag order
__device__ __forceinline__ int ppos(int jj) {
    return ((jj >> 2) & 1) | ((jj & 3) << 1);
}

// ---------------- K1: Wh = h @ W via 2-term-compensated tf32 mma -------------
// CTA: 128 rows x 64 cols (one head), 256 thr, 8 warps = q(4) x nh(2).
// Wh = Ahi@Bhi + Ahi@Blo + Alo@Bhi  (error ~2^-22). Writes g_Wh + g_Yp.
#define K1_AHI 0
#define K1_ALO (128 * 33)
#define K1_BHI (2 * 128 * 33)
#define K1_BLO (K1_BHI + 2048)
#define SMEM_K1 ((K1_BLO + 2048) * 4)    // 50176 B

__global__ __launch_bounds__(256) void k1_gemm(const float* __restrict__ h,
                                               const float* __restrict__ W) {
    extern __shared__ float sk1[];
    unsigned* sAhi = (unsigned*)(sk1 + K1_AHI);
    unsigned* sAlo = (unsigned*)(sk1 + K1_ALO);
    unsigned* sBhi = (unsigned*)(sk1 + K1_BHI);
    unsigned* sBlo = (unsigned*)(sk1 + K1_BLO);

    int t    = threadIdx.x;
    int lane = t & 31;
    int warp = t >> 5;
    int hh   = blockIdx.x;               // head
    int j0   = blockIdx.y * 128;         // node rows
    int n0   = hh * 64;
    int q    = warp >> 1;                // m-quarter
    int nh   = warp & 1;                 // n-half

    float acc[2][4][4];
#pragma unroll
    for (int it = 0; it < 2; it++)
#pragma unroll
        for (int n = 0; n < 4; n++)
#pragma unroll
            for (int c = 0; c < 4; c++) acc[it][n][c] = 0.f;

    for (int k0 = 0; k0 < IND; k0 += 32) {
        // ---- stage A (h tile 128x32, hi/lo) ----
        {
            int m  = t >> 1;
            int kh = (t & 1) * 16;
            const float* src = &h[(j0 + m) * IND + k0 + kh];
#pragma unroll
            for (int x = 0; x < 16; x++) {
                float v  = src[x];
                unsigned hi = tf32r(v);
                float lo = v - __uint_as_float(hi);
                sAhi[m * 33 + kh + x] = hi;
                sAlo[m * 33 + kh + x] = tf32r(lo);
            }
        }
        // ---- stage B (W tile 32x64, hi/lo, frag order) ----
        {
            int kl = t >> 3;             // 0..31
            int nb = (t & 7) * 8;        // 0..56
            int kk = kl >> 3, w = kl & 7, c = w & 3, v = w >> 2;
            const float* src = &W[(k0 + kl) * HD + n0 + nb];
#pragma unroll
            for (int x = 0; x < 8; x++) {
                int n = nb + x;
                float val = src[x];
                unsigned hi = tf32r(val);
                float lo = val - __uint_as_float(hi);
                int dst = ((kk * 8 + (n >> 3)) * 32 + (n & 7) * 4 + c) * 2 + v;
                sBhi[dst] = hi;
                sBlo[dst] = tf32r(lo);
            }
        }
        __syncthreads();

        // ---- compute ----
        int r = lane >> 2, c = lane & 3;
#pragma unroll
        for (int kk = 0; kk < 4; kk++) {
            int cb = kk * 8 + c;
            int rb0 = (q * 32 + r) * 33;
            unsigned ah0[4], ah1[4], al0[4], al1[4];
            ah0[0] = sAhi[rb0 + cb];            ah0[1] = sAhi[rb0 + 8 * 33 + cb];
            ah0[2] = sAhi[rb0 + cb + 4];        ah0[3] = sAhi[rb0 + 8 * 33 + cb + 4];
            ah1[0] = sAhi[rb0 + 16 * 33 + cb];  ah1[1] = sAhi[rb0 + 24 * 33 + cb];
            ah1[2] = sAhi[rb0 + 16 * 33 + cb + 4]; ah1[3] = sAhi[rb0 + 24 * 33 + cb + 4];
            al0[0] = sAlo[rb0 + cb];            al0[1] = sAlo[rb0 + 8 * 33 + cb];
            al0[2] = sAlo[rb0 + cb + 4];        al0[3] = sAlo[rb0 + 8 * 33 + cb + 4];
            al1[0] = sAlo[rb0 + 16 * 33 + cb];  al1[1] = sAlo[rb0 + 24 * 33 + cb];
            al1[2] = sAlo[rb0 + 16 * 33 + cb + 4]; al1[3] = sAlo[rb0 + 24 * 33 + cb + 4];
#pragma unroll
            for (int nt = 0; nt < 4; nt++) {
                int bidx = ((kk * 8 + nh * 4 + nt) * 32 + lane) * 2;
                unsigned bh0 = sBhi[bidx], bh1 = sBhi[bidx + 1];
                unsigned bl0 = sBlo[bidx], bl1 = sBlo[bidx + 1];
                mma8(acc[0][nt], ah0, bh0, bh1);
                mma8(acc[1][nt], ah1, bh0, bh1);
                mma8(acc[0][nt], ah0, bl0, bl1);
                mma8(acc[1][nt], ah1, bl0, bl1);
                mma8(acc[0][nt], al0, bh0, bh1);
                mma8(acc[1][nt], al1, bh0, bh1);
            }
        }
        __syncthreads();
    }

    // ---- epilogue: write g_Wh (fp32) and g_Yp (tf32 frag order) ----
    int r = lane >> 2, c = lane & 3;
#pragma unroll
    for (int it = 0; it < 2; it++) {
        int jg = j0 + q * 32 + it * 16 + r;
        int g0 = jg >> 3;
        int p0 = ppos(jg & 7);
        float* yb0 = g_Yp + (size_t)(hh * 512 + g0) * 512;
        float* yb1 = g_Yp + (size_t)(hh * 512 + g0 + 1) * 512;
#pragma unroll
        for (int nt = 0; nt < 4; nt++) {
            int d = nh * 32 + nt * 8 + c * 2;
            float v0 = acc[it][nt][0], v1 = acc[it][nt][1];
            float v2 = acc[it][nt][2], v3 = acc[it][nt][3];
            *(float2*)&g_Wh[(size_t)jg * HD + n0 + d]       = make_float2(v0, v1);
            *(float2*)&g_Wh[(size_t)(jg + 8) * HD + n0 + d] = make_float2(v2, v3);
            yb0[d * 8 + p0]       = __uint_as_float(tf32r(v0));
            yb0[(d + 1) * 8 + p0] = __uint_as_float(tf32r(v1));
            yb1[d * 8 + p0]       = __uint_as_float(tf32r(v2));
            yb1[(d + 1) * 8 + p0] = __uint_as_float(tf32r(v3));
        }
    }
}

// ---------------- K2: per-node attention logits + exps -----------------------
__global__ __launch_bounds__(256) void k2_e(const float* __restrict__ a) {
    int i = blockIdx.x;
    int t = threadIdx.x;
    int hh = t >> 6, d = t & 63;
    float v  = g_Wh[i * HD + t];
    float ei = v * a[hh * (2 * DD) + d];
    float ej = v * a[hh * (2 * DD) + DD + d];
#pragma unroll
    for (int o = 16; o > 0; o >>= 1) {
        ei += __shfl_down_sync(0xffffffffu, ei, o);
        ej += __shfl_down_sync(0xffffffffu, ej, o);
    }
    __shared__ float sei[8], sej[8];
    int w = t >> 5;
    if ((t & 31) == 0) { sei[w] = ei; sej[w] = ej; }
    __syncthreads();
    if (t < HH) {
        float EI = sei[2 * t] + sei[2 * t + 1];
        float EJ = sej[2 * t] + sej[2 * t + 1];
        g_Ei1[i * HH + t] = __expf(EI);
        g_Ei2[i * HH + t] = __expf(0.2f * EI);
        g_Ej1[i * HH + t] = __expf(EJ);
        g_Ej2[i * HH + t] = __expf(0.2f * EJ);
    }
}

// ---------------- K3: fused weight build + mma.sync tf32 contraction ---------
// (r10 best config, unchanged) 32 warps = h(4) x q(4) x nh(2); 64 regs; 128 CTAs.
#define SWBUF  (HH * BM * SWP)           // 18432 floats
#define OFF_E1 (2 * SWBUF)
#define OFF_E2 (OFF_E1 + 512)
#define OFF_J1 (OFF_E2 + 512)
#define OFF_J2 (OFF_J1 + 4096)
#define SMEM_K3 ((OFF_J2 + 4096) * 4)    // 184320 B

__global__ __launch_bounds__(1024, 1) void k3_main(const float* __restrict__ adj) {
    extern __shared__ float sm[];
    float* sE1  = sm + OFF_E1;
    float* sE2  = sm + OFF_E2;
    float* sEj1 = sm + OFF_J1;
    float* sEj2 = sm + OFF_J2;

    int t    = threadIdx.x;
    int lane = t & 31;
    int warp = t >> 5;
    int i0   = blockIdx.x * BM;
    int js   = blockIdx.y;
    int j0b  = js * (Nn / JSPLIT);
    int h    = warp & 3;                 // head
    int q    = (warp >> 2) & 3;          // m-quarter (32 rows)
    int nh   = warp >> 4;                // n-half (32 of 64 cols)

    if (t < 512) { sE1[t] = g_Ei1[i0 * HH + t]; sE2[t] = g_Ei2[i0 * HH + t]; }
#pragma unroll
    for (int p = 0; p < 4; p++) {        // whole js-slice Ej tables -> smem
        int idx = p * 1024 + t;
        sEj1[idx] = g_Ej1[j0b * HH + idx];
        sEj2[idx] = g_Ej2[j0b * HH + idx];
    }
    __syncthreads();

    float acc[2][4][4];                  // m32 x n32 per warp
#pragma unroll
    for (int it = 0; it < 2; it++)
#pragma unroll
        for (int n = 0; n < 4; n++)
#pragma unroll
            for (int c = 0; c < 4; c++) acc[it][n][c] = 0.f;
    float dA[2][2] = {{0.f, 0.f}, {0.f, 0.f}};

    int boff = (lane >> 2) * 8 + (lane & 3) * 2;

    // ---- build chunk 0 (each warp: 4 rows, all 4 heads) ----
    {
        float4 Ej1 = *(const float4*)&sEj1[lane * 4];
        float4 Ej2 = *(const float4*)&sEj2[lane * 4];
        unsigned* W0 = (unsigned*)sm;
#pragma unroll
        for (int r = 0; r < 4; r++) {
            int i = warp * 4 + r;
            float av = __ldg(&adj[(long)(i0 + i) * Nn + j0b + lane]);
            float em = (av == 0.f) ? 0.f : __expf(av);
            float4 e1 = *(const float4*)&sE1[i * 4];
            float4 e2 = *(const float4*)&sE2[i * 4];
            W0[0 * BM * SWP + i * SWP + lane] = tf32r(em * fmaxf(e1.x * Ej1.x, e2.x * Ej2.x));
            W0[1 * BM * SWP + i * SWP + lane] = tf32r(em * fmaxf(e1.y * Ej1.y, e2.y * Ej2.y));
            W0[2 * BM * SWP + i * SWP + lane] = tf32r(em * fmaxf(e1.z * Ej1.z, e2.z * Ej2.z));
            W0[3 * BM * SWP + i * SWP + lane] = tf32r(em * fmaxf(e1.w * Ej1.w, e2.w * Ej2.w));
        }
    }
    __syncthreads();

    for (int cc = 0; cc < NCH; cc++) {
        int buf = cc & 1;

        // ---- build chunk cc+1 into other buffer ----
        if (cc + 1 < NCH) {
            int jr0 = (cc + 1) * BK + lane;
            float4 Ej1 = *(const float4*)&sEj1[jr0 * 4];
            float4 Ej2 = *(const float4*)&sEj2[jr0 * 4];
            unsigned* W0 = (unsigned*)(sm + (buf ^ 1) * SWBUF);
            int j0 = j0b + (cc + 1) * BK;
#pragma unroll
            for (int r = 0; r < 4; r++) {
                int i = warp * 4 + r;
                float av = __ldg(&adj[(long)(i0 + i) * Nn + j0 + lane]);
                float em = (av == 0.f) ? 0.f : __expf(av);
                float4 e1 = *(const float4*)&sE1[i * 4];
                float4 e2 = *(const float4*)&sE2[i * 4];
                W0[0 * BM * SWP + i * SWP + lane] = tf32r(em * fmaxf(e1.x * Ej1.x, e2.x * Ej2.x));
                W0[1 * BM * SWP + i * SWP + lane] = tf32r(em * fmaxf(e1.y * Ej1.y, e2.y * Ej2.y));
                W0[2 * BM * SWP + i * SWP + lane] = tf32r(em * fmaxf(e1.z * Ej1.z, e2.z * Ej2.z));
                W0[3 * BM * SWP + i * SWP + lane] = tf32r(em * fmaxf(e1.w * Ej1.w, e2.w * Ej2.w));
            }
        }

        // ---- mma chunk cc from buf; B direct from L2-resident g_Yp ----
        {
            int gb = (j0b + cc * BK) >> 3;
            const unsigned* Wp = (const unsigned*)(sm + buf * SWBUF)
                                 + h * BM * SWP + (q * 32) * SWP;
            int r = lane >> 2;
#pragma unroll
            for (int k = 0; k < 4; k++) {
                int col = k * 8 + (lane & 3);
                unsigned a0[4], a1[4];
                a0[0] = Wp[(r +  0) * SWP + col];     a0[1] = Wp[(r +  8) * SWP + col];
                a0[2] = Wp[(r +  0) * SWP + col + 4]; a0[3] = Wp[(r +  8) * SWP + col + 4];
                a1[0] = Wp[(r + 16) * SWP + col];     a1[1] = Wp[(r + 24) * SWP + col];
                a1[2] = Wp[(r + 16) * SWP + col + 4]; a1[3] = Wp[(r + 24) * SWP + col + 4];
                if (nh == 0) {           // denominator partials on fma pipe
                    dA[0][0] += __uint_as_float(a0[0]) + __uint_as_float(a0[2]);
                    dA[0][1] += __uint_as_float(a0[1]) + __uint_as_float(a0[3]);
                    dA[1][0] += __uint_as_float(a1[0]) + __uint_as_float(a1[2]);
                    dA[1][1] += __uint_as_float(a1[1]) + __uint_as_float(a1[3]);
                }
                const float* Bb = g_Yp + (size_t)(h * 512 + gb + k) * 512 + nh * 4 * 64;
#pragma unroll
                for (int n = 0; n < 4; n++) {
                    float2 bv = *(const float2*)&Bb[n * 64 + boff];
                    unsigned b0 = __float_as_uint(bv.x), b1 = __float_as_uint(bv.y);
                    mma8(acc[0][n], a0, b0, b1);
                    mma8(acc[1][n], a1, b0, b1);
                }
            }
        }
        __syncthreads();
    }

    // ---- epilogue ----
    int rb = i0 + q * 32;
    int r  = lane >> 2;
    float* P = g_part[js];
#pragma unroll
    for (int it = 0; it < 2; it++) {
        int r0 = rb + it * 16 + r;
#pragma unroll
        for (int n = 0; n < 4; n++) {
            int cb = h * 64 + nh * 32 + n * 8 + (lane & 3) * 2;
            *(float2*)&P[(size_t)r0 * HD + cb]       = make_float2(acc[it][n][0], acc[it][n][1]);
            *(float2*)&P[(size_t)(r0 + 8) * HD + cb] = make_float2(acc[it][n][2], acc[it][n][3]);
        }
        if (nh == 0) {
            float d0 = dA[it][0], d1 = dA[it][1];
            d0 += __shfl_xor_sync(0xffffffffu, d0, 1);
            d0 += __shfl_xor_sync(0xffffffffu, d0, 2);
            d1 += __shfl_xor_sync(0xffffffffu, d1, 1);
            d1 += __shfl_xor_sync(0xffffffffu, d1, 2);
            if ((lane & 3) == 0) {
                g_denp[js][r0 * HH + h]       = d0;
                g_denp[js][(r0 + 8) * HH + h] = d1;
            }
        }
    }
}

// ---------------- K4: combine splits, normalize, ELU (float4) ----------------
__global__ __launch_bounds__(256) void k4_out(float* __restrict__ out) {
    int idx4 = blockIdx.x * 256 + threadIdx.x;   // float4 index
    int i    = idx4 >> 6;
    int hh   = (idx4 >> 4) & 3;
    int base = idx4 * 4;

    float4 n0 = *(const float4*)&g_part[0][base];
    float4 n1 = *(const float4*)&g_part[1][base];
    float4 n2 = *(const float4*)&g_part[2][base];
    float4 n3 = *(const float4*)&g_part[3][base];
    float den = g_denp[0][i * HH + hh] + g_denp[1][i * HH + hh]
              + g_denp[2][i * HH + hh] + g_denp[3][i * HH + hh];
    float4 wh = *(const float4*)&g_Wh[base];

    float4 num = make_float4(n0.x + n1.x + n2.x + n3.x,
                             n0.y + n1.y + n2.y + n3.y,
                             n0.z + n1.z + n2.z + n3.z,
                             n0.w + n1.w + n2.w + n3.w);
    float rd = (den != 0.f) ? (1.f / den) : 0.f;
    float vx = (den != 0.f) ? num.x * rd : wh.x;
    float vy = (den != 0.f) ? num.y * rd : wh.y;
    float vz = (den != 0.f) ? num.z * rd : wh.z;
    float vw = (den != 0.f) ? num.w * rd : wh.w;
    float4 o;
    o.x = (vx > 0.f) ? vx : expm1f(vx);
    o.y = (vy > 0.f) ? vy : expm1f(vy);
    o.z = (vz > 0.f) ? vz : expm1f(vz);
    o.w = (vw > 0.f) ? vw : expm1f(vw);
    *(float4*)&out[base] = o;
}

// ---------------- launch ------------------------------------------------------
extern "C" void kernel_launch(void* const* d_in, const int* in_sizes, int n_in,
                              void* d_out, int out_size) {
    const float* h   = (const float*)d_in[0];
    const float* adj = (const float*)d_in[1];
    const float* W   = (const float*)d_in[2];
    const float* a   = (const float*)d_in[3];
    float* out = (float*)d_out;

    k0_nop<<<1, 32>>>();

    cudaFuncSetAttribute((const void*)k1_gemm,
                         cudaFuncAttributeMaxDynamicSharedMemorySize, SMEM_K1);
    k1_gemm<<<dim3(HH, Nn / 128), 256, SMEM_K1>>>(h, W);

    k2_e<<<Nn, 256>>>(a);

    cudaFuncSetAttribute((const void*)k3_main,
                         cudaFuncAttributeMaxDynamicSharedMemorySize, SMEM_K3);
    k3_main<<<dim3(Nn / BM, JSPLIT), 1024, SMEM_K3>>>(adj);

    k4_out<<<Nn * HD / 4 / 256, 256>>>(out);
}

// round 15
// speedup vs baseline: 1.0700x; 1.0700x over previous
#include <cuda_runtime.h>
#include <cstdint>

#define Nn     4096
#define IND    256
#define HH     4
#define DD     64
#define HD     256
#define JSPLIT 4
#define BM     128
#define BK     32
#define NCH    ((Nn / JSPLIT) / BK)     // 32 chunks
#define SWP    36                        // sW row stride (floats) -> conflict-free frags

// ---------------- scratch (device globals; no allocation allowed) ------------
__device__ __align__(16) float g_Wh [Nn * HD];            // fp32 Wh [node][h*64+d]
__device__ __align__(16) float g_Yp [HH * 512 * DD * 8];  // tf32 [h][g][d][jj'] frag order
__device__ __align__(16) float g_Ei1[Nn * HH];            // exp(e_i)
__device__ __align__(16) float g_Ei2[Nn * HH];            // exp(0.2 e_i)
__device__ __align__(16) float g_Ej1[Nn * HH];            // exp(e_j)
__device__ __align__(16) float g_Ej2[Nn * HH];            // exp(0.2 e_j)
__device__ __align__(16) float g_part[JSPLIT][Nn * HD];
__device__ __align__(16) float g_denp[JSPLIT][Nn * HH];
__device__ int g_nop;

__device__ __forceinline__ unsigned tf32r(float x) {
    unsigned u;
    asm("cvt.rna.tf32.f32 %0, %1;" : "=r"(u) : "f"(x));
    return u;
}
__device__ __forceinline__ void mma8(float* c, const unsigned* a, unsigned b0, unsigned b1) {
    asm volatile(
        "mma.sync.aligned.m16n8k8.row.col.f32.tf32.tf32.f32 "
        "{%0,%1,%2,%3}, {%4,%5,%6,%7}, {%8,%9}, {%0,%1,%2,%3};"
        : "+f"(c[0]), "+f"(c[1]), "+f"(c[2]), "+f"(c[3])
        : "r"(a[0]), "r"(a[1]), "r"(a[2]), "r"(a[3]), "r"(b0), "r"(b1));
}

// dummy launch: keeps ncu's fixed capture slot on k3
__global__ void k0_nop() { g_nop = 0; }

// ---------------- K1: Wh = h @ W ; also emit fragment-ordered tf32 copy ------
__global__ __launch_bounds__(256) void k1_gemm(const float* __restrict__ h,
                                               const float* __restrict__ W) {
    __shared__ float As[16][64 + 4];
    __shared__ float Bs[16][64];
    __shared__ float til[64][68];
    int t  = threadIdx.x;
    int tx = t & 15, ty = t >> 4;
    int j0 = blockIdx.y * 64;
    int n0 = blockIdx.x * 64;
    float acc[4][4];
#pragma unroll
    for (int m = 0; m < 4; m++)
#pragma unroll
        for (int c = 0; c < 4; c++) acc[m][c] = 0.f;

    for (int k0 = 0; k0 < IND; k0 += 16) {
        int arow = t >> 2, akq = (t & 3) * 4;
        float4 av = *(const float4*)&h[(j0 + arow) * IND + k0 + akq];
        As[akq + 0][arow] = av.x; As[akq + 1][arow] = av.y;
        As[akq + 2][arow] = av.z; As[akq + 3][arow] = av.w;
        int brow = t >> 4, bcol = (t & 15) * 4;
        *(float4*)&Bs[brow][bcol] = *(const float4*)&W[(k0 + brow) * HD + n0 + bcol];
        __syncthreads();
#pragma unroll
        for (int kk = 0; kk < 16; kk++) {
            float a0 = As[kk][ty * 4 + 0], a1 = As[kk][ty * 4 + 1];
            float a2 = As[kk][ty * 4 + 2], a3 = As[kk][ty * 4 + 3];
            float4 b = *(float4*)&Bs[kk][tx * 4];
            acc[0][0] += a0 * b.x; acc[0][1] += a0 * b.y; acc[0][2] += a0 * b.z; acc[0][3] += a0 * b.w;
            acc[1][0] += a1 * b.x; acc[1][1] += a1 * b.y; acc[1][2] += a1 * b.z; acc[1][3] += a1 * b.w;
            acc[2][0] += a2 * b.x; acc[2][1] += a2 * b.y; acc[2][2] += a2 * b.z; acc[2][3] += a2 * b.w;
            acc[3][0] += a3 * b.x; acc[3][1] += a3 * b.y; acc[3][2] += a3 * b.z; acc[3][3] += a3 * b.w;
        }
        __syncthreads();
    }
#pragma unroll
    for (int m = 0; m < 4; m++) {
        *(float4*)&til[ty * 4 + m][tx * 4] =
            make_float4(acc[m][0], acc[m][1], acc[m][2], acc[m][3]);
#pragma unroll
        for (int c = 0; c < 4; c++)
            g_Wh[(j0 + ty * 4 + m) * HD + n0 + tx * 4 + c] = acc[m][c];
    }
    __syncthreads();

    int hh = blockIdx.x;
    float* dst = g_Yp + (hh * 512 + blockIdx.y * 8) * 512;
#pragma unroll
    for (int it = 0; it < 16; it++) {
        int idx = it * 256 + t;
        int jj  = ((idx & 1) << 2) | ((idx >> 1) & 3);   // inverse perm
        float v = til[(idx >> 9) * 8 + jj][(idx >> 3) & 63];
        dst[idx] = __uint_as_float(tf32r(v));
    }
}

// ---------------- K2: per-node attention logits + exps -----------------------
__global__ __launch_bounds__(256) void k2_e(const float* __restrict__ a) {
    int i = blockIdx.x;
    int t = threadIdx.x;
    int hh = t >> 6, d = t & 63;
    float v  = g_Wh[i * HD + t];
    float ei = v * a[hh * (2 * DD) + d];
    float ej = v * a[hh * (2 * DD) + DD + d];
#pragma unroll
    for (int o = 16; o > 0; o >>= 1) {
        ei += __shfl_down_sync(0xffffffffu, ei, o);
        ej += __shfl_down_sync(0xffffffffu, ej, o);
    }
    __shared__ float sei[8], sej[8];
    int w = t >> 5;
    if ((t & 31) == 0) { sei[w] = ei; sej[w] = ej; }
    __syncthreads();
    if (t < HH) {
        float EI = sei[2 * t] + sei[2 * t + 1];
        float EJ = sej[2 * t] + sej[2 * t + 1];
        g_Ei1[i * HH + t] = __expf(EI);
        g_Ei2[i * HH + t] = __expf(0.2f * EI);
        g_Ej1[i * HH + t] = __expf(EJ);
        g_Ej2[i * HH + t] = __expf(0.2f * EJ);
    }
}

// ---------------- K3: fused weight build + mma.sync tf32 contraction ---------
// (r10 best config, unchanged) 32 warps = h(4) x q(4) x nh(2); 64 regs; 128 CTAs.
#define SWBUF  (HH * BM * SWP)           // 18432 floats
#define OFF_E1 (2 * SWBUF)
#define OFF_E2 (OFF_E1 + 512)
#define OFF_J1 (OFF_E2 + 512)
#define OFF_J2 (OFF_J1 + 4096)
#define SMEM_K3 ((OFF_J2 + 4096) * 4)    // 184320 B

__global__ __launch_bounds__(1024, 1) void k3_main(const float* __restrict__ adj) {
    extern __shared__ float sm[];
    float* sE1  = sm + OFF_E1;
    float* sE2  = sm + OFF_E2;
    float* sEj1 = sm + OFF_J1;
    float* sEj2 = sm + OFF_J2;

    int t    = threadIdx.x;
    int lane = t & 31;
    int warp = t >> 5;
    int i0   = blockIdx.x * BM;
    int js   = blockIdx.y;
    int j0b  = js * (Nn / JSPLIT);
    int h    = warp & 3;                 // head
    int q    = (warp >> 2) & 3;          // m-quarter (32 rows)
    int nh   = warp >> 4;                // n-half (32 of 64 cols)

    if (t < 512) { sE1[t] = g_Ei1[i0 * HH + t]; sE2[t] = g_Ei2[i0 * HH + t]; }
#pragma unroll
    for (int p = 0; p < 4; p++) {        // whole js-slice Ej tables -> smem
        int idx = p * 1024 + t;
        sEj1[idx] = g_Ej1[j0b * HH + idx];
        sEj2[idx] = g_Ej2[j0b * HH + idx];
    }
    __syncthreads();

    float acc[2][4][4];                  // m32 x n32 per warp
#pragma unroll
    for (int it = 0; it < 2; it++)
#pragma unroll
        for (int n = 0; n < 4; n++)
#pragma unroll
            for (int c = 0; c < 4; c++) acc[it][n][c] = 0.f;
    float dA[2][2] = {{0.f, 0.f}, {0.f, 0.f}};

    int boff = (lane >> 2) * 8 + (lane & 3) * 2;

    // ---- build chunk 0 (each warp: 4 rows, all 4 heads) ----
    {
        float4 Ej1 = *(const float4*)&sEj1[lane * 4];
        float4 Ej2 = *(const float4*)&sEj2[lane * 4];
        unsigned* W0 = (unsigned*)sm;
#pragma unroll
        for (int r = 0; r < 4; r++) {
            int i = warp * 4 + r;
            float av = __ldg(&adj[(long)(i0 + i) * Nn + j0b + lane]);
            float em = (av == 0.f) ? 0.f : __expf(av);
            float4 e1 = *(const float4*)&sE1[i * 4];
            float4 e2 = *(const float4*)&sE2[i * 4];
            W0[0 * BM * SWP + i * SWP + lane] = tf32r(em * fmaxf(e1.x * Ej1.x, e2.x * Ej2.x));
            W0[1 * BM * SWP + i * SWP + lane] = tf32r(em * fmaxf(e1.y * Ej1.y, e2.y * Ej2.y));
            W0[2 * BM * SWP + i * SWP + lane] = tf32r(em * fmaxf(e1.z * Ej1.z, e2.z * Ej2.z));
            W0[3 * BM * SWP + i * SWP + lane] = tf32r(em * fmaxf(e1.w * Ej1.w, e2.w * Ej2.w));
        }
    }
    __syncthreads();

    for (int cc = 0; cc < NCH; cc++) {
        int buf = cc & 1;

        // ---- build chunk cc+1 into other buffer ----
        if (cc + 1 < NCH) {
            int jr0 = (cc + 1) * BK + lane;
            float4 Ej1 = *(const float4*)&sEj1[jr0 * 4];
            float4 Ej2 = *(const float4*)&sEj2[jr0 * 4];
            unsigned* W0 = (unsigned*)(sm + (buf ^ 1) * SWBUF);
            int j0 = j0b + (cc + 1) * BK;
#pragma unroll
            for (int r = 0; r < 4; r++) {
                int i = warp * 4 + r;
                float av = __ldg(&adj[(long)(i0 + i) * Nn + j0 + lane]);
                float em = (av == 0.f) ? 0.f : __expf(av);
                float4 e1 = *(const float4*)&sE1[i * 4];
                float4 e2 = *(const float4*)&sE2[i * 4];
                W0[0 * BM * SWP + i * SWP + lane] = tf32r(em * fmaxf(e1.x * Ej1.x, e2.x * Ej2.x));
                W0[1 * BM * SWP + i * SWP + lane] = tf32r(em * fmaxf(e1.y * Ej1.y, e2.y * Ej2.y));
                W0[2 * BM * SWP + i * SWP + lane] = tf32r(em * fmaxf(e1.z * Ej1.z, e2.z * Ej2.z));
                W0[3 * BM * SWP + i * SWP + lane] = tf32r(em * fmaxf(e1.w * Ej1.w, e2.w * Ej2.w));
            }
        }

        // ---- mma chunk cc from buf; B direct from L2-resident g_Yp ----
        {
            int gb = (j0b + cc * BK) >> 3;
            const unsigned* Wp = (const unsigned*)(sm + buf * SWBUF)
                                 + h * BM * SWP + (q * 32) * SWP;
            int r = lane >> 2;
#pragma unroll
            for (int k = 0; k < 4; k++) {
                int col = k * 8 + (lane & 3);
                unsigned a0[4], a1[4];
                a0[0] = Wp[(r +  0) * SWP + col];     a0[1] = Wp[(r +  8) * SWP + col];
                a0[2] = Wp[(r +  0) * SWP + col + 4]; a0[3] = Wp[(r +  8) * SWP + col + 4];
                a1[0] = Wp[(r + 16) * SWP + col];     a1[1] = Wp[(r + 24) * SWP + col];
                a1[2] = Wp[(r + 16) * SWP + col + 4]; a1[3] = Wp[(r + 24) * SWP + col + 4];
                if (nh == 0) {           // denominator partials on fma pipe
                    dA[0][0] += __uint_as_float(a0[0]) + __uint_as_float(a0[2]);
                    dA[0][1] += __uint_as_float(a0[1]) + __uint_as_float(a0[3]);
                    dA[1][0] += __uint_as_float(a1[0]) + __uint_as_float(a1[2]);
                    dA[1][1] += __uint_as_float(a1[1]) + __uint_as_float(a1[3]);
                }
                const float* Bb = g_Yp + (size_t)(h * 512 + gb + k) * 512 + nh * 4 * 64;
#pragma unroll
                for (int n = 0; n < 4; n++) {
                    float2 bv = *(const float2*)&Bb[n * 64 + boff];
                    unsigned b0 = __float_as_uint(bv.x), b1 = __float_as_uint(bv.y);
                    mma8(acc[0][n], a0, b0, b1);
                    mma8(acc[1][n], a1, b0, b1);
                }
            }
        }
        __syncthreads();
    }

    // ---- epilogue ----
    int rb = i0 + q * 32;
    int r  = lane >> 2;
    float* P = g_part[js];
#pragma unroll
    for (int it = 0; it < 2; it++) {
        int r0 = rb + it * 16 + r;
#pragma unroll
        for (int n = 0; n < 4; n++) {
            int cb = h * 64 + nh * 32 + n * 8 + (lane & 3) * 2;
            *(float2*)&P[(size_t)r0 * HD + cb]       = make_float2(acc[it][n][0], acc[it][n][1]);
            *(float2*)&P[(size_t)(r0 + 8) * HD + cb] = make_float2(acc[it][n][2], acc[it][n][3]);
        }
        if (nh == 0) {
            float d0 = dA[it][0], d1 = dA[it][1];
            d0 += __shfl_xor_sync(0xffffffffu, d0, 1);
            d0 += __shfl_xor_sync(0xffffffffu, d0, 2);
            d1 += __shfl_xor_sync(0xffffffffu, d1, 1);
            d1 += __shfl_xor_sync(0xffffffffu, d1, 2);
            if ((lane & 3) == 0) {
                g_denp[js][r0 * HH + h]       = d0;
                g_denp[js][(r0 + 8) * HH + h] = d1;
            }
        }
    }
}

// ---------------- K4: combine splits, normalize, ELU (float4) ----------------
__global__ __launch_bounds__(256) void k4_out(float* __restrict__ out) {
    int idx4 = blockIdx.x * 256 + threadIdx.x;   // float4 index
    int i    = idx4 >> 6;
    int hh   = (idx4 >> 4) & 3;
    int base = idx4 * 4;

    float4 n0 = *(const float4*)&g_part[0][base];
    float4 n1 = *(const float4*)&g_part[1][base];
    float4 n2 = *(const float4*)&g_part[2][base];
    float4 n3 = *(const float4*)&g_part[3][base];
    float den = g_denp[0][i * HH + hh] + g_denp[1][i * HH + hh]
              + g_denp[2][i * HH + hh] + g_denp[3][i * HH + hh];
    float4 wh = *(const float4*)&g_Wh[base];

    // preserve r10 summation order: ((s0+s1)+s2)+s3 elementwise
    float numx = n0.x + n1.x + n2.x + n3.x;
    float numy = n0.y + n1.y + n2.y + n3.y;
    float numz = n0.z + n1.z + n2.z + n3.z;
    float numw = n0.w + n1.w + n2.w + n3.w;

    float vx = (den != 0.f) ? (numx / den) : wh.x;
    float vy = (den != 0.f) ? (numy / den) : wh.y;
    float vz = (den != 0.f) ? (numz / den) : wh.z;
    float vw = (den != 0.f) ? (numw / den) : wh.w;
    float4 o;
    o.x = (vx > 0.f) ? vx : expm1f(vx);
    o.y = (vy > 0.f) ? vy : expm1f(vy);
    o.z = (vz > 0.f) ? vz : expm1f(vz);
    o.w = (vw > 0.f) ? vw : expm1f(vw);
    *(float4*)&out[base] = o;
}

// ---------------- launch ------------------------------------------------------
extern "C" void kernel_launch(void* const* d_in, const int* in_sizes, int n_in,
                              void* d_out, int out_size) {
    const float* h   = (const float*)d_in[0];
    const float* adj = (const float*)d_in[1];
    const float* W   = (const float*)d_in[2];
    const float* a   = (const float*)d_in[3];
    float* out = (float*)d_out;

    k0_nop<<<1, 32>>>();
    k1_gemm<<<dim3(HD / 64, Nn / 64), 256>>>(h, W);
    k2_e<<<Nn, 256>>>(a);

    cudaFuncSetAttribute((const void*)k3_main,
                         cudaFuncAttributeMaxDynamicSharedMemorySize, SMEM_K3);
    k3_main<<<dim3(Nn / BM, JSPLIT), 1024, SMEM_K3>>>(adj);

    k4_out<<<Nn * HD / 4 / 256, 256>>>(out);
}

// round 16
// speedup vs baseline: 1.0918x; 1.0204x over previous
#include <cuda_runtime.h>
#include <cstdint>

#define Nn     4096
#define IND    256
#define HH     4
#define DD     64
#define HD     256
#define JSPLIT 4
#define BM     128
#define BK     32
#define NCH    ((Nn / JSPLIT) / BK)     // 32 chunks
#define SWP    36                        // sW row stride (floats) -> conflict-free frags

// ---------------- scratch (device globals; no allocation allowed) ------------
__device__ __align__(16) float g_Wh [Nn * HD];            // fp32 Wh [node][h*64+d]
__device__ __align__(16) float g_Yp [HH * 512 * DD * 8];  // tf32 [h][g][d][jj'] frag order
__device__ __align__(16) float g_Ei1[Nn * HH];            // exp(e_i)
__device__ __align__(16) float g_Ei2[Nn * HH];            // exp(0.2 e_i)
__device__ __align__(16) float g_Ej1[Nn * HH];            // exp(e_j)
__device__ __align__(16) float g_Ej2[Nn * HH];            // exp(0.2 e_j)
__device__ __align__(16) float g_part[JSPLIT][Nn * HD];
__device__ __align__(16) float g_denp[JSPLIT][Nn * HH];
__device__ int g_nop;

__device__ __forceinline__ unsigned tf32r(float x) {
    unsigned u;
    asm("cvt.rna.tf32.f32 %0, %1;" : "=r"(u) : "f"(x));
    return u;
}
__device__ __forceinline__ void mma8(float* c, const unsigned* a, unsigned b0, unsigned b1) {
    asm volatile(
        "mma.sync.aligned.m16n8k8.row.col.f32.tf32.tf32.f32 "
        "{%0,%1,%2,%3}, {%4,%5,%6,%7}, {%8,%9}, {%0,%1,%2,%3};"
        : "+f"(c[0]), "+f"(c[1]), "+f"(c[2]), "+f"(c[3])
        : "r"(a[0]), "r"(a[1]), "r"(a[2]), "r"(a[3]), "r"(b0), "r"(b1));
}

// dummy launches: keep ncu's fixed capture slot (4th launch) on k3
__global__ void k0_nop()  { g_nop = 0; }
__global__ void k0_nop2() { g_nop = 0; }

// ---------------- K1: Wh = h @ W ; frag-ordered tf32 copy; fused logits ------
__global__ __launch_bounds__(256) void k1_gemm(const float* __restrict__ h,
                                               const float* __restrict__ W,
                                               const float* __restrict__ a) {
    __shared__ float As[16][64 + 4];
    __shared__ float Bs[16][64];
    __shared__ float til[64][68];
    int t  = threadIdx.x;
    int tx = t & 15, ty = t >> 4;
    int j0 = blockIdx.y * 64;
    int n0 = blockIdx.x * 64;
    float acc[4][4];
#pragma unroll
    for (int m = 0; m < 4; m++)
#pragma unroll
        for (int c = 0; c < 4; c++) acc[m][c] = 0.f;

    for (int k0 = 0; k0 < IND; k0 += 16) {
        int arow = t >> 2, akq = (t & 3) * 4;
        float4 av = *(const float4*)&h[(j0 + arow) * IND + k0 + akq];
        As[akq + 0][arow] = av.x; As[akq + 1][arow] = av.y;
        As[akq + 2][arow] = av.z; As[akq + 3][arow] = av.w;
        int brow = t >> 4, bcol = (t & 15) * 4;
        *(float4*)&Bs[brow][bcol] = *(const float4*)&W[(k0 + brow) * HD + n0 + bcol];
        __syncthreads();
#pragma unroll
        for (int kk = 0; kk < 16; kk++) {
            float a0 = As[kk][ty * 4 + 0], a1 = As[kk][ty * 4 + 1];
            float a2 = As[kk][ty * 4 + 2], a3 = As[kk][ty * 4 + 3];
            float4 b = *(float4*)&Bs[kk][tx * 4];
            acc[0][0] += a0 * b.x; acc[0][1] += a0 * b.y; acc[0][2] += a0 * b.z; acc[0][3] += a0 * b.w;
            acc[1][0] += a1 * b.x; acc[1][1] += a1 * b.y; acc[1][2] += a1 * b.z; acc[1][3] += a1 * b.w;
            acc[2][0] += a2 * b.x; acc[2][1] += a2 * b.y; acc[2][2] += a2 * b.z; acc[2][3] += a2 * b.w;
            acc[3][0] += a3 * b.x; acc[3][1] += a3 * b.y; acc[3][2] += a3 * b.z; acc[3][3] += a3 * b.w;
        }
        __syncthreads();
    }
#pragma unroll
    for (int m = 0; m < 4; m++) {
        *(float4*)&til[ty * 4 + m][tx * 4] =
            make_float4(acc[m][0], acc[m][1], acc[m][2], acc[m][3]);
#pragma unroll
        for (int c = 0; c < 4; c++)
            g_Wh[(j0 + ty * 4 + m) * HD + n0 + tx * 4 + c] = acc[m][c];
    }
    __syncthreads();

    int hh = blockIdx.x;
    float* dst = g_Yp + (hh * 512 + blockIdx.y * 8) * 512;
#pragma unroll
    for (int it = 0; it < 16; it++) {
        int idx = it * 256 + t;
        int jj  = ((idx & 1) << 2) | ((idx >> 1) & 3);   // inverse perm
        float v = til[(idx >> 9) * 8 + jj][(idx >> 3) & 63];
        dst[idx] = __uint_as_float(tf32r(v));
    }

    // ---- fused k2: per-row attention logits for this head (reads til) ----
    if (t < 64) {
        const float* ai = a + hh * (2 * DD);
        float ei = 0.f, ej = 0.f;
#pragma unroll 8
        for (int c = 0; c < 64; c++) {
            float v = til[t][c];
            ei += v * ai[c];
            ej += v * ai[DD + c];
        }
        int node = (j0 + t) * HH + hh;
        g_Ei1[node] = __expf(ei);
        g_Ei2[node] = __expf(0.2f * ei);
        g_Ej1[node] = __expf(ej);
        g_Ej2[node] = __expf(0.2f * ej);
    }
}

// ---------------- K3: fused weight build + mma.sync tf32 contraction ---------
// (r10 best config) 32 warps = h(4) x q(4) x nh(2); 64 regs; 128 CTAs; plus
// L2 prefetch of chunk cc+2's adj tile issued during MMA(cc).
#define SWBUF  (HH * BM * SWP)           // 18432 floats
#define OFF_E1 (2 * SWBUF)
#define OFF_E2 (OFF_E1 + 512)
#define OFF_J1 (OFF_E2 + 512)
#define OFF_J2 (OFF_J1 + 4096)
#define SMEM_K3 ((OFF_J2 + 4096) * 4)    // 184320 B

__global__ __launch_bounds__(1024, 1) void k3_main(const float* __restrict__ adj) {
    extern __shared__ float sm[];
    float* sE1  = sm + OFF_E1;
    float* sE2  = sm + OFF_E2;
    float* sEj1 = sm + OFF_J1;
    float* sEj2 = sm + OFF_J2;

    int t    = threadIdx.x;
    int lane = t & 31;
    int warp = t >> 5;
    int i0   = blockIdx.x * BM;
    int js   = blockIdx.y;
    int j0b  = js * (Nn / JSPLIT);
    int h    = warp & 3;                 // head
    int q    = (warp >> 2) & 3;          // m-quarter (32 rows)
    int nh   = warp >> 4;                // n-half (32 of 64 cols)

    if (t < 512) { sE1[t] = g_Ei1[i0 * HH + t]; sE2[t] = g_Ei2[i0 * HH + t]; }
#pragma unroll
    for (int p = 0; p < 4; p++) {        // whole js-slice Ej tables -> smem
        int idx = p * 1024 + t;
        sEj1[idx] = g_Ej1[j0b * HH + idx];
        sEj2[idx] = g_Ej2[j0b * HH + idx];
    }
    __syncthreads();

    float acc[2][4][4];                  // m32 x n32 per warp
#pragma unroll
    for (int it = 0; it < 2; it++)
#pragma unroll
        for (int n = 0; n < 4; n++)
#pragma unroll
            for (int c = 0; c < 4; c++) acc[it][n][c] = 0.f;
    float dA[2][2] = {{0.f, 0.f}, {0.f, 0.f}};

    int boff = (lane >> 2) * 8 + (lane & 3) * 2;
    const float* aRow = adj + (long)(i0 + warp * 4) * Nn + j0b + lane;

    // ---- build chunk 0 (each warp: 4 rows, all 4 heads) ----
    {
        float4 Ej1 = *(const float4*)&sEj1[lane * 4];
        float4 Ej2 = *(const float4*)&sEj2[lane * 4];
        unsigned* W0 = (unsigned*)sm;
#pragma unroll
        for (int r = 0; r < 4; r++) {
            int i = warp * 4 + r;
            float av = __ldg(&adj[(long)(i0 + i) * Nn + j0b + lane]);
            float em = (av == 0.f) ? 0.f : __expf(av);
            float4 e1 = *(const float4*)&sE1[i * 4];
            float4 e2 = *(const float4*)&sE2[i * 4];
            W0[0 * BM * SWP + i * SWP + lane] = tf32r(em * fmaxf(e1.x * Ej1.x, e2.x * Ej2.x));
            W0[1 * BM * SWP + i * SWP + lane] = tf32r(em * fmaxf(e1.y * Ej1.y, e2.y * Ej2.y));
            W0[2 * BM * SWP + i * SWP + lane] = tf32r(em * fmaxf(e1.z * Ej1.z, e2.z * Ej2.z));
            W0[3 * BM * SWP + i * SWP + lane] = tf32r(em * fmaxf(e1.w * Ej1.w, e2.w * Ej2.w));
        }
    }
    __syncthreads();

    for (int cc = 0; cc < NCH; cc++) {
        int buf = cc & 1;

        // ---- build chunk cc+1 into other buffer ----
        if (cc + 1 < NCH) {
            int jr0 = (cc + 1) * BK + lane;
            float4 Ej1 = *(const float4*)&sEj1[jr0 * 4];
            float4 Ej2 = *(const float4*)&sEj2[jr0 * 4];
            unsigned* W0 = (unsigned*)(sm + (buf ^ 1) * SWBUF);
            int j0 = j0b + (cc + 1) * BK;
#pragma unroll
            for (int r = 0; r < 4; r++) {
                int i = warp * 4 + r;
                float av = __ldg(&adj[(long)(i0 + i) * Nn + j0 + lane]);
                float em = (av == 0.f) ? 0.f : __expf(av);
                float4 e1 = *(const float4*)&sE1[i * 4];
                float4 e2 = *(const float4*)&sE2[i * 4];
                W0[0 * BM * SWP + i * SWP + lane] = tf32r(em * fmaxf(e1.x * Ej1.x, e2.x * Ej2.x));
                W0[1 * BM * SWP + i * SWP + lane] = tf32r(em * fmaxf(e1.y * Ej1.y, e2.y * Ej2.y));
                W0[2 * BM * SWP + i * SWP + lane] = tf32r(em * fmaxf(e1.z * Ej1.z, e2.z * Ej2.z));
                W0[3 * BM * SWP + i * SWP + lane] = tf32r(em * fmaxf(e1.w * Ej1.w, e2.w * Ej2.w));
            }
        }

        // ---- L2-prefetch chunk cc+2's adj (consumed by build in iter cc+1) ----
        if (cc + 2 < NCH) {
            const float* pf = aRow + (cc + 2) * BK;
#pragma unroll
            for (int r = 0; r < 4; r++)
                asm volatile("prefetch.global.L2 [%0];" :: "l"(pf + (long)r * Nn));
        }

        // ---- mma chunk cc from buf; B direct from L2-resident g_Yp ----
        {
            int gb = (j0b + cc * BK) >> 3;
            const unsigned* Wp = (const unsigned*)(sm + buf * SWBUF)
                                 + h * BM * SWP + (q * 32) * SWP;
            int r = lane >> 2;
#pragma unroll
            for (int k = 0; k < 4; k++) {
                int col = k * 8 + (lane & 3);
                unsigned a0[4], a1[4];
                a0[0] = Wp[(r +  0) * SWP + col];     a0[1] = Wp[(r +  8) * SWP + col];
                a0[2] = Wp[(r +  0) * SWP + col + 4]; a0[3] = Wp[(r +  8) * SWP + col + 4];
                a1[0] = Wp[(r + 16) * SWP + col];     a1[1] = Wp[(r + 24) * SWP + col];
                a1[2] = Wp[(r + 16) * SWP + col + 4]; a1[3] = Wp[(r + 24) * SWP + col + 4];
                if (nh == 0) {           // denominator partials on fma pipe
                    dA[0][0] += __uint_as_float(a0[0]) + __uint_as_float(a0[2]);
                    dA[0][1] += __uint_as_float(a0[1]) + __uint_as_float(a0[3]);
                    dA[1][0] += __uint_as_float(a1[0]) + __uint_as_float(a1[2]);
                    dA[1][1] += __uint_as_float(a1[1]) + __uint_as_float(a1[3]);
                }
                const float* Bb = g_Yp + (size_t)(h * 512 + gb + k) * 512 + nh * 4 * 64;
#pragma unroll
                for (int n = 0; n < 4; n++) {
                    float2 bv = *(const float2*)&Bb[n * 64 + boff];
                    unsigned b0 = __float_as_uint(bv.x), b1 = __float_as_uint(bv.y);
                    mma8(acc[0][n], a0, b0, b1);
                    mma8(acc[1][n], a1, b0, b1);
                }
            }
        }
        __syncthreads();
    }

    // ---- epilogue ----
    int rb = i0 + q * 32;
    int r  = lane >> 2;
    float* P = g_part[js];
#pragma unroll
    for (int it = 0; it < 2; it++) {
        int r0 = rb + it * 16 + r;
#pragma unroll
        for (int n = 0; n < 4; n++) {
            int cb = h * 64 + nh * 32 + n * 8 + (lane & 3) * 2;
            *(float2*)&P[(size_t)r0 * HD + cb]       = make_float2(acc[it][n][0], acc[it][n][1]);
            *(float2*)&P[(size_t)(r0 + 8) * HD + cb] = make_float2(acc[it][n][2], acc[it][n][3]);
        }
        if (nh == 0) {
            float d0 = dA[it][0], d1 = dA[it][1];
            d0 += __shfl_xor_sync(0xffffffffu, d0, 1);
            d0 += __shfl_xor_sync(0xffffffffu, d0, 2);
            d1 += __shfl_xor_sync(0xffffffffu, d1, 1);
            d1 += __shfl_xor_sync(0xffffffffu, d1, 2);
            if ((lane & 3) == 0) {
                g_denp[js][r0 * HH + h]       = d0;
                g_denp[js][(r0 + 8) * HH + h] = d1;
            }
        }
    }
}

// ---------------- K4: combine splits, normalize, ELU (float4) ----------------
__global__ __launch_bounds__(256) void k4_out(float* __restrict__ out) {
    int idx4 = blockIdx.x * 256 + threadIdx.x;   // float4 index
    int i    = idx4 >> 6;
    int hh   = (idx4 >> 4) & 3;
    int base = idx4 * 4;

    float4 n0 = *(const float4*)&g_part[0][base];
    float4 n1 = *(const float4*)&g_part[1][base];
    float4 n2 = *(const float4*)&g_part[2][base];
    float4 n3 = *(const float4*)&g_part[3][base];
    float den = g_denp[0][i * HH + hh] + g_denp[1][i * HH + hh]
              + g_denp[2][i * HH + hh] + g_denp[3][i * HH + hh];
    float4 wh = *(const float4*)&g_Wh[base];

    float numx = n0.x + n1.x + n2.x + n3.x;
    float numy = n0.y + n1.y + n2.y + n3.y;
    float numz = n0.z + n1.z + n2.z + n3.z;
    float numw = n0.w + n1.w + n2.w + n3.w;

    float vx = (den != 0.f) ? (numx / den) : wh.x;
    float vy = (den != 0.f) ? (numy / den) : wh.y;
    float vz = (den != 0.f) ? (numz / den) : wh.z;
    float vw = (den != 0.f) ? (numw / den) : wh.w;
    float4 o;
    o.x = (vx > 0.f) ? vx : expm1f(vx);
    o.y = (vy > 0.f) ? vy : expm1f(vy);
    o.z = (vz > 0.f) ? vz : expm1f(vz);
    o.w = (vw > 0.f) ? vw : expm1f(vw);
    *(float4*)&out[base] = o;
}

// ---------------- launch ------------------------------------------------------
extern "C" void kernel_launch(void* const* d_in, const int* in_sizes, int n_in,
                              void* d_out, int out_size) {
    const float* h   = (const float*)d_in[0];
    const float* adj = (const float*)d_in[1];
    const float* W   = (const float*)d_in[2];
    const float* a   = (const float*)d_in[3];
    float* out = (float*)d_out;

    k0_nop<<<1, 32>>>();
    k0_nop2<<<1, 32>>>();
    k1_gemm<<<dim3(HD / 64, Nn / 64), 256>>>(h, W, a);

    cudaFuncSetAttribute((const void*)k3_main,
                         cudaFuncAttributeMaxDynamicSharedMemorySize, SMEM_K3);
    k3_main<<<dim3(Nn / BM, JSPLIT), 1024, SMEM_K3>>>(adj);

    k4_out<<<Nn * HD / 4 / 256, 256>>>(out);
}